// round 1
// baseline (speedup 1.0000x reference)
#include <cuda_runtime.h>
#include <cuda_bf16.h>
#include <cstdint>

// Problem constants (fixed by setup_inputs)
#define KCL 65536      // number of clusters (GEMM N)
#define DD  256        // feature dim
#define OO  256        // output dim
#define BB  1024       // batch rows (GEMM M)
#define TOPK 32
#define KK  512        // GEMM reduction dim (2*DD)
#define CAND_CAP 2048

// ---------------- scratch (static device globals; no allocations) ----------
__device__ __nv_bfloat16 g_W[(size_t)KCL * KK];          // 64 MB
__device__ __nv_bfloat16 g_A[(size_t)BB * KK];           // 1 MB
__device__ float g_cterm[KCL];
__device__ float g_logn[KCL];
__device__ float g_S[(size_t)BB * KCL];                  // 256 MB fp32 scores
__device__ unsigned g_rowmax[BB];
__device__ int g_cand[(size_t)BB * CAND_CAP];
__device__ int g_cnt[BB];

__device__ __forceinline__ unsigned fkey(float f) {
    unsigned u = __float_as_uint(f);
    return (u & 0x80000000u) ? ~u : (u | 0x80000000u);
}
__device__ __forceinline__ float keyf(unsigned k) {
    unsigned u = (k & 0x80000000u) ? (k & 0x7FFFFFFFu) : ~k;
    return __uint_as_float(u);
}

#define NEG_INF (__int_as_float(0xff800000))
#define LOG2PI 1.8378770664093455f

// ---------------- init --------------------------------------------------
__global__ void init_kernel() {
    int i = blockIdx.x * blockDim.x + threadIdx.x;
    if (i < BB) { g_rowmax[i] = 0u; g_cnt[i] = 0; }
}

// ---------------- prep A = [x*x, x] (bf16) ------------------------------
__global__ void prep_x_kernel(const float* __restrict__ x) {
    int b = blockIdx.x;
    int d = threadIdx.x;
    float v = x[b * DD + d];
    g_A[b * KK + d]      = __float2bfloat16(v * v);
    g_A[b * KK + DD + d] = __float2bfloat16(v);
}

// ---------------- prep W = [-0.5*ivar, mu*ivar], cterm, logn ------------
__global__ __launch_bounds__(256) void prep_w_kernel(const float* __restrict__ mean,
                                                     const float* __restrict__ stddev) {
    int k = blockIdx.x;
    int d = threadIdx.x;
    float mu = mean[k * DD + d];
    float sg = stddev[k * DD + d];
    float iv = 1.0f / (sg * sg);
    g_W[(size_t)k * KK + d]      = __float2bfloat16(-0.5f * iv);
    g_W[(size_t)k * KK + DD + d] = __float2bfloat16(mu * iv);

    float s1 = mu * mu * iv;
    float s2 = logf(sg);
    #pragma unroll
    for (int o = 16; o; o >>= 1) {
        s1 += __shfl_xor_sync(0xffffffffu, s1, o);
        s2 += __shfl_xor_sync(0xffffffffu, s2, o);
    }
    __shared__ float sh1[8], sh2[8];
    int wid = threadIdx.x >> 5, lane = threadIdx.x & 31;
    if (lane == 0) { sh1[wid] = s1; sh2[wid] = s2; }
    __syncthreads();
    if (threadIdx.x == 0) {
        float t1 = 0.f, t2 = 0.f;
        #pragma unroll
        for (int i = 0; i < 8; i++) { t1 += sh1[i]; t2 += sh2[i]; }
        g_logn[k]  = t2;
        g_cterm[k] = -0.5f * t1 - t2 - 128.0f * LOG2PI;
    }
}

// ---------------- bf16 mma GEMM: S = A @ W^T + cterm --------------------
#define BM 128
#define BN 128
#define KC 64
#define SA 72   // padded smem stride (elems); 144B rows: 16B-aligned, conflict-free frags

__device__ __forceinline__ void mma16816(float* c, const uint32_t* a, const uint32_t* b) {
    asm volatile(
        "mma.sync.aligned.m16n8k16.row.col.f32.bf16.bf16.f32 "
        "{%0,%1,%2,%3}, {%4,%5,%6,%7}, {%8,%9}, {%0,%1,%2,%3};\n"
        : "+f"(c[0]), "+f"(c[1]), "+f"(c[2]), "+f"(c[3])
        : "r"(a[0]), "r"(a[1]), "r"(a[2]), "r"(a[3]), "r"(b[0]), "r"(b[1]));
}

__global__ __launch_bounds__(256) void gemm_kernel() {
    __shared__ __nv_bfloat16 As[BM * SA];
    __shared__ __nv_bfloat16 Ws[BN * SA];

    int bn = blockIdx.x;              // 0..511
    int bm = blockIdx.y;              // 0..7
    int tid = threadIdx.x;
    int wid = tid >> 5, lane = tid & 31;
    int wm = wid & 3, wn = wid >> 2;  // warp tile: rows wm*32, cols wn*64
    int g = lane >> 2, t4 = lane & 3;

    float acc[2][8][4];
    #pragma unroll
    for (int mt = 0; mt < 2; mt++)
        #pragma unroll
        for (int nt = 0; nt < 8; nt++)
            #pragma unroll
            for (int i = 0; i < 4; i++) acc[mt][nt][i] = 0.f;

    for (int kc = 0; kc < KK / KC; kc++) {
        #pragma unroll
        for (int j = 0; j < 4; j++) {
            int v = tid + j * 256;          // 0..1023
            int r = v >> 3;                 // 0..127
            int c = (v & 7) * 8;            // 0..56
            uint4 va = *(const uint4*)&g_A[(size_t)(bm * BM + r) * KK + kc * KC + c];
            *(uint4*)&As[r * SA + c] = va;
            uint4 vw = *(const uint4*)&g_W[(size_t)(bn * BN + r) * KK + kc * KC + c];
            *(uint4*)&Ws[r * SA + c] = vw;
        }
        __syncthreads();

        #pragma unroll
        for (int s = 0; s < KC / 16; s++) {
            int kb = s * 16;
            uint32_t af[2][4], bfr[8][2];
            #pragma unroll
            for (int mt = 0; mt < 2; mt++) {
                const __nv_bfloat16* p = &As[(wm * 32 + mt * 16 + g) * SA + kb + t4 * 2];
                af[mt][0] = *(const uint32_t*)(p);
                af[mt][1] = *(const uint32_t*)(p + 8 * SA);
                af[mt][2] = *(const uint32_t*)(p + 8);
                af[mt][3] = *(const uint32_t*)(p + 8 * SA + 8);
            }
            #pragma unroll
            for (int nt = 0; nt < 8; nt++) {
                const __nv_bfloat16* p = &Ws[(wn * 64 + nt * 8 + g) * SA + kb + t4 * 2];
                bfr[nt][0] = *(const uint32_t*)(p);
                bfr[nt][1] = *(const uint32_t*)(p + 8);
            }
            #pragma unroll
            for (int mt = 0; mt < 2; mt++)
                #pragma unroll
                for (int nt = 0; nt < 8; nt++)
                    mma16816(acc[mt][nt], af[mt], bfr[nt]);
        }
        __syncthreads();
    }

    // epilogue: add cterm, store fp32 scores, fold per-row max into global
    int n0 = bn * BN + wn * 64;
    float rmax[2][2] = {{NEG_INF, NEG_INF}, {NEG_INF, NEG_INF}};
    #pragma unroll
    for (int mt = 0; mt < 2; mt++) {
        int row0 = bm * BM + wm * 32 + mt * 16 + g;
        #pragma unroll
        for (int nt = 0; nt < 8; nt++) {
            int col = n0 + nt * 8 + t4 * 2;
            float2 ct = *(const float2*)&g_cterm[col];
            float v0 = acc[mt][nt][0] + ct.x;
            float v1 = acc[mt][nt][1] + ct.y;
            float v2 = acc[mt][nt][2] + ct.x;
            float v3 = acc[mt][nt][3] + ct.y;
            *(float2*)&g_S[(size_t)row0 * KCL + col]       = make_float2(v0, v1);
            *(float2*)&g_S[(size_t)(row0 + 8) * KCL + col] = make_float2(v2, v3);
            rmax[mt][0] = fmaxf(rmax[mt][0], fmaxf(v0, v1));
            rmax[mt][1] = fmaxf(rmax[mt][1], fmaxf(v2, v3));
        }
    }
    #pragma unroll
    for (int mt = 0; mt < 2; mt++)
        #pragma unroll
        for (int h = 0; h < 2; h++) {
            float v = rmax[mt][h];
            v = fmaxf(v, __shfl_xor_sync(0xffffffffu, v, 1));
            v = fmaxf(v, __shfl_xor_sync(0xffffffffu, v, 2));
            if (t4 == 0)
                atomicMax(&g_rowmax[bm * BM + wm * 32 + mt * 16 + h * 8 + g], fkey(v));
        }
}

// ---------------- candidate selection (per row) -------------------------
// Histogram (M - s) in 0.125-wide bins, find bin holding rank-32, collect
// everything >= that threshold minus a 2.0 safety margin (covers bf16 GEMM err).
__global__ __launch_bounds__(256) void select_kernel() {
    int b = blockIdx.x;
    int tid = threadIdx.x;
    __shared__ unsigned hist[2048];
    __shared__ int s_b32;
    __shared__ int s_cnt;
    for (int i = tid; i < 2048; i += 256) hist[i] = 0u;
    if (tid == 0) s_cnt = 0;
    __syncthreads();

    float M = keyf(g_rowmax[b]);
    const float* S = &g_S[(size_t)b * KCL];
    for (int i = tid; i < KCL; i += 256) {
        float d = M - S[i];
        if (d < 256.0f) atomicAdd(&hist[(int)(d * 8.0f)], 1u);
    }
    __syncthreads();
    if (tid == 0) {
        unsigned cum = 0; int bidx = 2047;
        for (int i = 0; i < 2048; i++) { cum += hist[i]; if (cum >= TOPK) { bidx = i; break; } }
        s_b32 = bidx;
    }
    __syncthreads();
    float T = M - (float)(s_b32 + 1) * 0.125f - 2.0f;
    for (int i = tid; i < KCL; i += 256) {
        if (S[i] >= T) {
            int p = atomicAdd(&s_cnt, 1);
            if (p < CAND_CAP) g_cand[(size_t)b * CAND_CAP + p] = i;
        }
    }
    __syncthreads();
    if (tid == 0) g_cnt[b] = min(s_cnt, CAND_CAP);
}

// ---------------- exact rescore + top-32 + softmax + gather -------------
__global__ __launch_bounds__(256) void rescore_kernel(const float* __restrict__ x,
                                                      const float* __restrict__ mean,
                                                      const float* __restrict__ stddev,
                                                      const float* __restrict__ outputs,
                                                      float* __restrict__ out) {
    int b = blockIdx.x;
    int tid = threadIdx.x, wid = tid >> 5, lane = tid & 31;
    __shared__ float xs[DD];
    __shared__ float lp_s[CAND_CAP];
    __shared__ float redv[256];
    __shared__ int   redi[256];
    __shared__ int   selk[TOPK];
    __shared__ float selw[TOPK];

    xs[tid] = x[b * DD + tid];
    int cnt = g_cnt[b];
    __syncthreads();

    // exact fp32 log-prob for each candidate (one warp per candidate)
    for (int j = wid; j < cnt; j += 8) {
        int k = g_cand[(size_t)b * CAND_CAP + j];
        float acc = 0.f;
        #pragma unroll
        for (int t = 0; t < 8; t++) {
            int d = lane + t * 32;
            float mu = mean[k * DD + d];
            float sg = stddev[k * DD + d];
            float iv = 1.0f / (sg * sg);
            float df = xs[d] - mu;
            acc += df * df * iv;
        }
        #pragma unroll
        for (int o = 16; o; o >>= 1) acc += __shfl_xor_sync(0xffffffffu, acc, o);
        if (lane == 0) lp_s[j] = -0.5f * acc - g_logn[k] - 128.0f * LOG2PI;
    }
    __syncthreads();

    // exact top-32 among candidates
    for (int it = 0; it < TOPK; it++) {
        float bv = NEG_INF; int bi = -1;
        for (int j = tid; j < cnt; j += 256)
            if (lp_s[j] > bv) { bv = lp_s[j]; bi = j; }
        redv[tid] = bv; redi[tid] = bi;
        __syncthreads();
        #pragma unroll
        for (int o = 128; o; o >>= 1) {
            if (tid < o && redv[tid + o] > redv[tid]) {
                redv[tid] = redv[tid + o]; redi[tid] = redi[tid + o];
            }
            __syncthreads();
        }
        if (tid == 0) {
            int j = redi[0];
            selk[it] = g_cand[(size_t)b * CAND_CAP + j];
            selw[it] = redv[0];         // lp for now
            lp_s[j] = NEG_INF;
        }
        __syncthreads();
    }

    // softmax over the 32 (descending lp; selw[0] is the max)
    if (tid == 0) {
        float m = selw[0], z = 0.f;
        #pragma unroll
        for (int i = 0; i < TOPK; i++) { float e = expf(selw[i] - m); selw[i] = e; z += e; }
        float iz = 1.0f / z;
        #pragma unroll
        for (int i = 0; i < TOPK; i++) selw[i] *= iz;
    }
    __syncthreads();

    // weighted gather: out[b, o] = sum_i w_i * outputs[k_i, o]
    float acc = 0.f;
    #pragma unroll 8
    for (int i = 0; i < TOPK; i++)
        acc += selw[i] * outputs[selk[i] * OO + tid];
    out[b * OO + tid] = acc;
}

// ---------------- launch -----------------------------------------------
extern "C" void kernel_launch(void* const* d_in, const int* in_sizes, int n_in,
                              void* d_out, int out_size) {
    const float* x       = (const float*)d_in[0];
    const float* mean    = (const float*)d_in[1];
    const float* stddev  = (const float*)d_in[2];
    const float* outputs = (const float*)d_in[3];
    float* out = (float*)d_out;
    (void)in_sizes; (void)n_in; (void)out_size;

    init_kernel<<<4, 256>>>();
    prep_x_kernel<<<BB, 256>>>(x);
    prep_w_kernel<<<KCL, 256>>>(mean, stddev);
    gemm_kernel<<<dim3(KCL / BN, BB / BM), 256>>>();
    select_kernel<<<BB, 256>>>();
    rescore_kernel<<<BB, 256>>>(x, mean, stddev, outputs, out);
}

// round 3
// speedup vs baseline: 1.3243x; 1.3243x over previous
#include <cuda_runtime.h>
#include <cuda_bf16.h>
#include <cuda_fp16.h>
#include <cstdint>

// Problem constants (fixed by setup_inputs)
#define KCL 65536      // number of clusters (GEMM N)
#define DD  256        // feature dim
#define OO  256        // output dim
#define BB  1024       // batch rows (GEMM M)
#define TOPK 32
#define KK  512        // GEMM reduction dim (2*DD)
#define CAND_CAP 2048

// ---------------- scratch (static device globals; no allocations) ----------
__device__ __nv_bfloat16 g_W[(size_t)KCL * KK];          // 64 MB
__device__ __nv_bfloat16 g_A[(size_t)BB * KK];           // 1 MB
__device__ float g_cterm[KCL];
__device__ float g_logn[KCL];
__device__ __half g_S[(size_t)BB * KCL];                 // 128 MB fp16 scores
__device__ unsigned g_rowmax[BB];
__device__ int g_cand[(size_t)BB * CAND_CAP];
__device__ int g_cnt[BB];

__device__ __forceinline__ unsigned fkey(float f) {
    unsigned u = __float_as_uint(f);
    return (u & 0x80000000u) ? ~u : (u | 0x80000000u);
}
__device__ __forceinline__ float keyf(unsigned k) {
    unsigned u = (k & 0x80000000u) ? (k & 0x7FFFFFFFu) : ~k;
    return __uint_as_float(u);
}

#define NEG_INF (__int_as_float(0xff800000))
#define LOG2PI 1.8378770664093455f

// ---------------- init --------------------------------------------------
__global__ void init_kernel() {
    int i = blockIdx.x * blockDim.x + threadIdx.x;
    if (i < BB) { g_rowmax[i] = 0u; g_cnt[i] = 0; }
}

// ---------------- prep A = [x*x, x] (bf16) ------------------------------
__global__ void prep_x_kernel(const float* __restrict__ x) {
    int b = blockIdx.x;
    int d = threadIdx.x;
    float v = x[b * DD + d];
    g_A[b * KK + d]      = __float2bfloat16(v * v);
    g_A[b * KK + DD + d] = __float2bfloat16(v);
}

// ---------------- prep W = [-0.5*ivar, mu*ivar], cterm, logn ------------
__global__ __launch_bounds__(256) void prep_w_kernel(const float* __restrict__ mean,
                                                     const float* __restrict__ stddev) {
    int k = blockIdx.x;
    int d = threadIdx.x;
    float mu = mean[k * DD + d];
    float sg = stddev[k * DD + d];
    float iv = __fdividef(1.0f, sg * sg);
    g_W[(size_t)k * KK + d]      = __float2bfloat16(-0.5f * iv);
    g_W[(size_t)k * KK + DD + d] = __float2bfloat16(mu * iv);

    float s1 = mu * mu * iv;
    float s2 = __logf(sg);
    #pragma unroll
    for (int o = 16; o; o >>= 1) {
        s1 += __shfl_xor_sync(0xffffffffu, s1, o);
        s2 += __shfl_xor_sync(0xffffffffu, s2, o);
    }
    __shared__ float sh1[8], sh2[8];
    int wid = threadIdx.x >> 5, lane = threadIdx.x & 31;
    if (lane == 0) { sh1[wid] = s1; sh2[wid] = s2; }
    __syncthreads();
    if (threadIdx.x == 0) {
        float t1 = 0.f, t2 = 0.f;
        #pragma unroll
        for (int i = 0; i < 8; i++) { t1 += sh1[i]; t2 += sh2[i]; }
        g_logn[k]  = t2;
        g_cterm[k] = -0.5f * t1 - t2 - 128.0f * LOG2PI;
    }
}

// ---------------- bf16 mma GEMM: S = A @ W^T + cterm --------------------
#define BM 128
#define BN 128
#define KC 64
#define SA 72   // padded smem stride (elems); 144B rows: 16B-aligned, conflict-free

#define A_STG (BM * SA)                 // elems per A stage
#define W_STG (BN * SA)
#define W_BASE (2 * A_STG)              // layout: [A0][A1][W0][W1]
#define SMEM_BYTES ((2 * A_STG + 2 * W_STG) * 2)

__device__ __forceinline__ void mma16816(float* c, const uint32_t* a, const uint32_t* b) {
    asm volatile(
        "mma.sync.aligned.m16n8k16.row.col.f32.bf16.bf16.f32 "
        "{%0,%1,%2,%3}, {%4,%5,%6,%7}, {%8,%9}, {%0,%1,%2,%3};\n"
        : "+f"(c[0]), "+f"(c[1]), "+f"(c[2]), "+f"(c[3])
        : "r"(a[0]), "r"(a[1]), "r"(a[2]), "r"(a[3]), "r"(b[0]), "r"(b[1]));
}

__device__ __forceinline__ void ldsm4(uint32_t& r0, uint32_t& r1, uint32_t& r2, uint32_t& r3,
                                      uint32_t addr) {
    asm volatile("ldmatrix.sync.aligned.m8n8.x4.shared.b16 {%0,%1,%2,%3}, [%4];\n"
                 : "=r"(r0), "=r"(r1), "=r"(r2), "=r"(r3) : "r"(addr));
}

__device__ __forceinline__ void cp_async16(uint32_t smem_dst, const void* gmem_src) {
    asm volatile("cp.async.cg.shared.global [%0], [%1], 16;\n" :: "r"(smem_dst), "l"(gmem_src));
}

__global__ __launch_bounds__(256, 2) void gemm_kernel() {
    extern __shared__ __nv_bfloat16 sh[];
    uint32_t smem_u32 = (uint32_t)__cvta_generic_to_shared(sh);

    int bm = blockIdx.x;              // 0..7   (fast dim -> W tile reused across bm in L2)
    int bn = blockIdx.y;              // 0..511
    int tid = threadIdx.x;
    int wid = tid >> 5, lane = tid & 31;
    int wm = wid & 3, wn = wid >> 2;  // warp tile: rows wm*32, cols wn*64
    int g = lane >> 2, t4 = lane & 3;

    // per-thread LDSM address components (bytes, relative to stage base)
    uint32_t aBase = (uint32_t)(((wm * 32 + (lane & 15)) * SA + (lane >> 4) * 8) * 2);
    uint32_t bBase = (uint32_t)(((wn * 64 + (lane & 7) + ((lane >> 4) << 3)) * SA
                                 + ((lane >> 3) & 1) * 8) * 2);

    // global load coordinates (4 x 16B per thread per operand per stage)
    int r0v = tid >> 3;               // row for j=0 (rows step 32 per j)
    int cv  = (tid & 7) * 8;          // col elems

    float acc[2][8][4];
    #pragma unroll
    for (int mt = 0; mt < 2; mt++)
        #pragma unroll
        for (int nt = 0; nt < 8; nt++)
            #pragma unroll
            for (int i = 0; i < 4; i++) acc[mt][nt][i] = 0.f;

    auto load_stage = [&](int kc, int st) {
        uint32_t aDst = smem_u32 + (uint32_t)(st * A_STG * 2);
        uint32_t wDst = smem_u32 + (uint32_t)((W_BASE + st * W_STG) * 2);
        #pragma unroll
        for (int j = 0; j < 4; j++) {
            int r = r0v + j * 32;
            cp_async16(aDst + (uint32_t)((r * SA + cv) * 2),
                       &g_A[(size_t)(bm * BM + r) * KK + kc * KC + cv]);
            cp_async16(wDst + (uint32_t)((r * SA + cv) * 2),
                       &g_W[(size_t)(bn * BN + r) * KK + kc * KC + cv]);
        }
    };

    load_stage(0, 0);
    asm volatile("cp.async.commit_group;\n");

    for (int kc = 0; kc < KK / KC; kc++) {
        if (kc + 1 < KK / KC) load_stage(kc + 1, (kc + 1) & 1);
        asm volatile("cp.async.commit_group;\n");
        asm volatile("cp.async.wait_group 1;\n");
        __syncthreads();

        uint32_t aStage = smem_u32 + (uint32_t)((kc & 1) * A_STG * 2) + aBase;
        uint32_t wStage = smem_u32 + (uint32_t)((W_BASE + (kc & 1) * W_STG) * 2) + bBase;

        #pragma unroll
        for (int s = 0; s < KC / 16; s++) {
            int kb = s * 16;
            uint32_t af[2][4], bfr[8][2];
            #pragma unroll
            for (int mt = 0; mt < 2; mt++)
                ldsm4(af[mt][0], af[mt][1], af[mt][2], af[mt][3],
                      aStage + (uint32_t)((mt * 16 * SA + kb) * 2));
            #pragma unroll
            for (int p = 0; p < 4; p++)
                ldsm4(bfr[2 * p][0], bfr[2 * p][1], bfr[2 * p + 1][0], bfr[2 * p + 1][1],
                      wStage + (uint32_t)((p * 16 * SA + kb) * 2));
            #pragma unroll
            for (int mt = 0; mt < 2; mt++)
                #pragma unroll
                for (int nt = 0; nt < 8; nt++)
                    mma16816(acc[mt][nt], af[mt], bfr[nt]);
        }
        __syncthreads();
    }

    // epilogue: add cterm, store fp16 scores, fold per-row max into global
    int n0 = bn * BN + wn * 64;
    float rmax[2][2] = {{NEG_INF, NEG_INF}, {NEG_INF, NEG_INF}};
    #pragma unroll
    for (int mt = 0; mt < 2; mt++) {
        int row0 = bm * BM + wm * 32 + mt * 16 + g;
        #pragma unroll
        for (int nt = 0; nt < 8; nt++) {
            int col = n0 + nt * 8 + t4 * 2;
            float2 ct = *(const float2*)&g_cterm[col];
            float v0 = acc[mt][nt][0] + ct.x;
            float v1 = acc[mt][nt][1] + ct.y;
            float v2 = acc[mt][nt][2] + ct.x;
            float v3 = acc[mt][nt][3] + ct.y;
            *(__half2*)&g_S[(size_t)row0 * KCL + col]       = __floats2half2_rn(v0, v1);
            *(__half2*)&g_S[(size_t)(row0 + 8) * KCL + col] = __floats2half2_rn(v2, v3);
            rmax[mt][0] = fmaxf(rmax[mt][0], fmaxf(v0, v1));
            rmax[mt][1] = fmaxf(rmax[mt][1], fmaxf(v2, v3));
        }
    }
    #pragma unroll
    for (int mt = 0; mt < 2; mt++)
        #pragma unroll
        for (int h = 0; h < 2; h++) {
            float v = rmax[mt][h];
            v = fmaxf(v, __shfl_xor_sync(0xffffffffu, v, 1));
            v = fmaxf(v, __shfl_xor_sync(0xffffffffu, v, 2));
            if (t4 == 0)
                atomicMax(&g_rowmax[bm * BM + wm * 32 + mt * 16 + h * 8 + g], fkey(v));
        }
}

// ---------------- candidate selection (per row, fp16 scores) -------------
__global__ __launch_bounds__(256) void select_kernel() {
    int b = blockIdx.x;
    int tid = threadIdx.x;
    __shared__ unsigned hist[2048];
    __shared__ int s_b32;
    __shared__ int s_cnt;
    for (int i = tid; i < 2048; i += 256) hist[i] = 0u;
    if (tid == 0) s_cnt = 0;
    __syncthreads();

    float M = keyf(g_rowmax[b]);
    const uint4* S4 = (const uint4*)&g_S[(size_t)b * KCL];   // 8 halves per load
    for (int i = tid; i < KCL / 8; i += 256) {
        uint4 u = S4[i];
        const __half2* h = (const __half2*)&u;
        #pragma unroll
        for (int p = 0; p < 4; p++) {
            float2 f = __half22float2(h[p]);
            float d0 = fmaxf(M - f.x, 0.f);
            float d1 = fmaxf(M - f.y, 0.f);
            if (d0 < 256.0f) atomicAdd(&hist[(int)(d0 * 8.0f)], 1u);
            if (d1 < 256.0f) atomicAdd(&hist[(int)(d1 * 8.0f)], 1u);
        }
    }
    __syncthreads();
    if (tid == 0) {
        unsigned cum = 0; int bidx = 2047;
        for (int i = 0; i < 2048; i++) { cum += hist[i]; if (cum >= TOPK) { bidx = i; break; } }
        s_b32 = bidx;
    }
    __syncthreads();
    float T = M - (float)(s_b32 + 1) * 0.125f - 3.0f;   // 3.0 margin: bf16 gemm + fp16 store
    for (int i = tid; i < KCL / 8; i += 256) {
        uint4 u = S4[i];
        const __half2* h = (const __half2*)&u;
        #pragma unroll
        for (int p = 0; p < 4; p++) {
            float2 f = __half22float2(h[p]);
            if (f.x >= T) {
                int q = atomicAdd(&s_cnt, 1);
                if (q < CAND_CAP) g_cand[(size_t)b * CAND_CAP + q] = i * 8 + p * 2;
            }
            if (f.y >= T) {
                int q = atomicAdd(&s_cnt, 1);
                if (q < CAND_CAP) g_cand[(size_t)b * CAND_CAP + q] = i * 8 + p * 2 + 1;
            }
        }
    }
    __syncthreads();
    if (tid == 0) g_cnt[b] = min(s_cnt, CAND_CAP);
}

// ---------------- exact rescore + top-32 + softmax + gather -------------
__global__ __launch_bounds__(256) void rescore_kernel(const float* __restrict__ x,
                                                      const float* __restrict__ mean,
                                                      const float* __restrict__ stddev,
                                                      const float* __restrict__ outputs,
                                                      float* __restrict__ out) {
    int b = blockIdx.x;
    int tid = threadIdx.x, wid = tid >> 5, lane = tid & 31;
    __shared__ float xs[DD];
    __shared__ float lp_s[CAND_CAP];
    __shared__ float redv[256];
    __shared__ int   redi[256];
    __shared__ int   selk[TOPK];
    __shared__ float selw[TOPK];

    xs[tid] = x[b * DD + tid];
    int cnt = g_cnt[b];
    __syncthreads();

    // exact fp32 log-prob for each candidate (one warp per candidate)
    for (int j = wid; j < cnt; j += 8) {
        int k = g_cand[(size_t)b * CAND_CAP + j];
        float acc = 0.f;
        #pragma unroll
        for (int t = 0; t < 8; t++) {
            int d = lane + t * 32;
            float mu = mean[k * DD + d];
            float sg = stddev[k * DD + d];
            float iv = 1.0f / (sg * sg);
            float df = xs[d] - mu;
            acc += df * df * iv;
        }
        #pragma unroll
        for (int o = 16; o; o >>= 1) acc += __shfl_xor_sync(0xffffffffu, acc, o);
        if (lane == 0) lp_s[j] = -0.5f * acc - g_logn[k] - 128.0f * LOG2PI;
    }
    __syncthreads();

    // exact top-32 among candidates
    for (int it = 0; it < TOPK; it++) {
        float bv = NEG_INF; int bi = -1;
        for (int j = tid; j < cnt; j += 256)
            if (lp_s[j] > bv) { bv = lp_s[j]; bi = j; }
        redv[tid] = bv; redi[tid] = bi;
        __syncthreads();
        #pragma unroll
        for (int o = 128; o; o >>= 1) {
            if (tid < o && redv[tid + o] > redv[tid]) {
                redv[tid] = redv[tid + o]; redi[tid] = redi[tid + o];
            }
            __syncthreads();
        }
        if (tid == 0) {
            int j = redi[0];
            selk[it] = g_cand[(size_t)b * CAND_CAP + j];
            selw[it] = redv[0];
            lp_s[j] = NEG_INF;
        }
        __syncthreads();
    }

    // softmax over the 32 (descending lp; selw[0] is the max)
    if (tid == 0) {
        float m = selw[0], z = 0.f;
        #pragma unroll
        for (int i = 0; i < TOPK; i++) { float e = expf(selw[i] - m); selw[i] = e; z += e; }
        float iz = 1.0f / z;
        #pragma unroll
        for (int i = 0; i < TOPK; i++) selw[i] *= iz;
    }
    __syncthreads();

    // weighted gather: out[b, o] = sum_i w_i * outputs[k_i, o]
    float acc = 0.f;
    #pragma unroll 8
    for (int i = 0; i < TOPK; i++)
        acc += selw[i] * outputs[selk[i] * OO + tid];
    out[b * OO + tid] = acc;
}

// ---------------- launch -----------------------------------------------
extern "C" void kernel_launch(void* const* d_in, const int* in_sizes, int n_in,
                              void* d_out, int out_size) {
    const float* x       = (const float*)d_in[0];
    const float* mean    = (const float*)d_in[1];
    const float* stddev  = (const float*)d_in[2];
    const float* outputs = (const float*)d_in[3];
    float* out = (float*)d_out;
    (void)in_sizes; (void)n_in; (void)out_size;

    cudaFuncSetAttribute(gemm_kernel, cudaFuncAttributeMaxDynamicSharedMemorySize, SMEM_BYTES);

    init_kernel<<<4, 256>>>();
    prep_x_kernel<<<BB, 256>>>(x);
    prep_w_kernel<<<KCL, 256>>>(mean, stddev);
    gemm_kernel<<<dim3(BB / BM, KCL / BN), 256, SMEM_BYTES>>>();
    select_kernel<<<BB, 256>>>();
    rescore_kernel<<<BB, 256>>>(x, mean, stddev, outputs, out);
}